// round 11
// baseline (speedup 1.0000x reference)
#include <cuda_runtime.h>
#include <cuda_bf16.h>

#define Bz 32
#define Nn 384          // H*W = 12*32
#define Cc 512
#define Dd 512
#define Ee 256
#define Vv 600
#define GJ 2048         // 4*D
#define NSTEP 191
#define EOS_TOK 130

// ----------------------------- scratch (device globals, no allocation) ------
__device__ float g_Wv[Bz * Nn * Dd];          // 24 MB   enc @ W_v, precomputed
__device__ float g_gp[16 * Bz * GJ];          // 16 MB   gates partials [ks][b][2048]
__device__ float g_op[8 * Bz * Dd];           // o_t partials [ks][b][d]
__device__ float g_hx[Bz * Dd];
__device__ float g_cx[Bz * Dd];
__device__ float g_oprev[Bz * Dd];
__device__ float g_q[Bz * Dd];
__device__ float g_ctx[Bz * Dd];
__device__ float g_sc[Bz * Nn];
__device__ int   g_tok[NSTEP * Bz];

// grid barrier state
__device__ unsigned g_count = 0;
__device__ volatile unsigned g_gen = 0;

__device__ __forceinline__ float sigf(float x) { return 1.0f / (1.0f + expf(-x)); }

__device__ __forceinline__ void gsync(int nblk) {
    __syncthreads();
    if (threadIdx.x == 0) {
        __threadfence();
        unsigned gen = g_gen;
        unsigned t = atomicInc(&g_count, (unsigned)(nblk - 1)); // wraps to 0 at nblk-1
        if (t == (unsigned)(nblk - 1)) {
            __threadfence();
            g_gen = gen + 1;                 // release
        } else {
            while (g_gen == gen) { }         // spin (volatile load)
            __threadfence();                 // acquire
        }
    }
    __syncthreads();
}

// ============================ the whole decoder ==============================
__global__ void __launch_bounds__(256, 2) k_all(
    const float* __restrict__ enc, const int* __restrict__ tgt,
    const float* __restrict__ emb,
    const float* __restrict__ Wih, const float* __restrict__ bih,
    const float* __restrict__ Whh, const float* __restrict__ bhh,
    const float* __restrict__ Wh,  const float* __restrict__ Wvw,
    const float* __restrict__ vvec,
    const float* __restrict__ Wc,  const float* __restrict__ bc,
    const float* __restrict__ Wout,const float* __restrict__ bout,
    float* __restrict__ out_logits, float* __restrict__ out_alpha, int nblk)
{
    __shared__ float sh[4096];                       // 16 KB, reused per phase
    const int tid = threadIdx.x;
    const int bid = blockIdx.x;

    // -------------------- prologue: Wv GEMM + init + tokens -----------------
    // jobs: [0,384) Wv 128x128 tiles; 384 tokens; [385,397) zero hx/cx/oprev
    for (int job = bid; job < 397; job += nblk) {
        if (job < 384) {
            int bm = job >> 2, bn = job & 3;
            int tm = tid / 16, tn = tid % 16;
            float acc[8][8];
#pragma unroll
            for (int i = 0; i < 8; i++)
#pragma unroll
                for (int j = 0; j < 8; j++) acc[i][j] = 0.0f;
            const float* Ag = enc + (size_t)(bm * 128) * 512;
            const float* Bg = Wvw + bn * 128;
            float* As = sh;            // [8][128]
            float* Bs = sh + 1024;     // [8][128]
            for (int k0 = 0; k0 < 512; k0 += 8) {
                {
                    int r = tid >> 1, s = tid & 1;
                    float4 a = *(const float4*)(Ag + (size_t)r * 512 + k0 + s * 4);
                    As[(s * 4 + 0) * 128 + r] = a.x; As[(s * 4 + 1) * 128 + r] = a.y;
                    As[(s * 4 + 2) * 128 + r] = a.z; As[(s * 4 + 3) * 128 + r] = a.w;
                }
                {
                    int kk = tid >> 5, c4 = tid & 31;
                    float4 bv = *(const float4*)(Bg + (size_t)(k0 + kk) * 512 + c4 * 4);
                    *(float4*)&Bs[kk * 128 + c4 * 4] = bv;
                }
                __syncthreads();
#pragma unroll
                for (int kk = 0; kk < 8; kk++) {
                    float a[8], b[8];
                    *(float4*)(a)     = *(float4*)&As[kk * 128 + tm * 8];
                    *(float4*)(a + 4) = *(float4*)&As[kk * 128 + tm * 8 + 4];
                    *(float4*)(b)     = *(float4*)&Bs[kk * 128 + tn * 8];
                    *(float4*)(b + 4) = *(float4*)&Bs[kk * 128 + tn * 8 + 4];
#pragma unroll
                    for (int i = 0; i < 8; i++)
#pragma unroll
                        for (int j = 0; j < 8; j++) acc[i][j] += a[i] * b[j];
                }
                __syncthreads();
            }
            float* Cg = g_Wv + (size_t)(bm * 128) * 512 + bn * 128;
#pragma unroll
            for (int i = 0; i < 8; i++) {
                int r = tm * 8 + i;
#pragma unroll
                for (int j = 0; j < 8; j += 4) {
                    float4 o = make_float4(acc[i][j], acc[i][j+1], acc[i][j+2], acc[i][j+3]);
                    *(float4*)(Cg + (size_t)r * 512 + tn * 8 + j) = o;
                }
            }
        } else if (job == 384) {
            // token precompute (int64/int32 autodetect: int64 high words are 0)
            if (tid == 0) {
                int nz = 0;
                for (int i = 1; i < 64; i += 2) nz |= tgt[i];
                ((int*)sh)[0] = (nz == 0) ? 1 : 0;
            }
            __syncthreads();
            int is64 = ((int*)sh)[0];
            if (tid < Bz) {
                int b = tid, fin = 0;
                g_tok[b] = 0;                         // sos
                for (int t = 0; t < NSTEP - 1; t++) {
                    int idx = b * 192 + t + 1;
                    int nt = is64 ? tgt[idx * 2] : tgt[idx];
                    fin |= (nt == EOS_TOK);
                    g_tok[(t + 1) * Bz + b] = fin ? 0 : nt;
                }
            }
        } else {
            int base = (job - 385) * 4096;            // 12 jobs x 4096 = 49152
            for (int i = tid; i < 4096; i += 256) {
                int idx = base + i;
                if (idx < 16384)        g_hx[idx] = 0.0f;
                else if (idx < 32768)   g_cx[idx - 16384] = 0.0f;
                else                    g_oprev[idx - 32768] = 0.0f;
            }
        }
        __syncthreads();
    }
    gsync(nblk);

    // ============================== step loop ===============================
    for (int t = 0; t < NSTEP; t++) {

        // ---- gates split-K GEMM: 512 jobs (32 jt x 16 ks) ----
        for (int job = bid; job < 512; job += nblk) {
            int jt = job & 31, ks = job >> 5;
            int kbase, klen;
            if (ks < 8) { kbase = ks * 96;             klen = 96; }
            else        { kbase = 768 + (ks - 8) * 64; klen = 64; }
            float* xs = sh;                            // [klen][32]
            for (int i = tid; i < klen * 32; i += 256) {
                int kk = i >> 5, b = i & 31;
                int k = kbase + kk;
                float xv;
                if (k < 256)      { int tok = g_tok[t * Bz + b]; xv = emb[tok * Ee + k]; }
                else if (k < 768) { xv = g_oprev[b * Dd + (k - 256)]; }
                else              { xv = g_hx[b * Dd + (k - 768)]; }
                xs[kk * 32 + b] = xv;
            }
            __syncthreads();
            int jj = tid & 63, bq = tid >> 6;
            int j = jt * 64 + jj;
            const float* Wp = (ks < 8) ? (Wih + (size_t)kbase * GJ + j)
                                       : (Whh + (size_t)(kbase - 768) * GJ + j);
            float acc[8];
#pragma unroll
            for (int i = 0; i < 8; i++) acc[i] = 0.0f;
#pragma unroll 4
            for (int kk = 0; kk < klen; kk++) {
                float w = Wp[(size_t)kk * GJ];
                float4 x0 = *(float4*)&xs[kk * 32 + bq * 8];
                float4 x1 = *(float4*)&xs[kk * 32 + bq * 8 + 4];
                acc[0] += w * x0.x; acc[1] += w * x0.y; acc[2] += w * x0.z; acc[3] += w * x0.w;
                acc[4] += w * x1.x; acc[5] += w * x1.y; acc[6] += w * x1.z; acc[7] += w * x1.w;
            }
#pragma unroll
            for (int i = 0; i < 8; i++)
                g_gp[((size_t)ks * Bz + bq * 8 + i) * GJ + j] = acc[i];
            __syncthreads();
        }
        gsync(nblk);

        // ---- LSTM elementwise (reduce 16 partials) + zero q/ctx ----
        for (int idx = bid * 256 + tid; idx < 16384; idx += nblk * 256) {
            int d = idx & 511;
            int b = idx >> 9;
            float gi = bih[d] + bhh[d];
            float gf = bih[d + 512] + bhh[d + 512];
            float gg = bih[d + 1024] + bhh[d + 1024];
            float go = bih[d + 1536] + bhh[d + 1536];
#pragma unroll
            for (int s = 0; s < 16; s++) {
                const float* gp = g_gp + ((size_t)s * Bz + b) * GJ;
                gi += gp[d];
                gf += gp[d + 512];
                gg += gp[d + 1024];
                go += gp[d + 1536];
            }
            float c = g_cx[idx];
            c = sigf(gf) * c + sigf(gi) * tanhf(gg);
            float h = sigf(go) * tanhf(c);
            g_cx[idx] = c;
            g_hx[idx] = h;
            g_q[idx] = 0.0f;
            g_ctx[idx] = 0.0f;
        }
        gsync(nblk);

        // ---- q = hx @ W_h: 64 jobs (8 dt x 8 ks), atomic accumulate ----
        for (int job = bid; job < 64; job += nblk) {
            int dt = job & 7, ks = job >> 3;
            float* xs = sh;                            // [64][32]
            for (int i = tid; i < 64 * 32; i += 256) {
                int kk = i >> 5, b = i & 31;
                xs[kk * 32 + b] = g_hx[b * Dd + ks * 64 + kk];
            }
            __syncthreads();
            int dl = tid & 63, bq = tid >> 6;
            int d = dt * 64 + dl;
            const float* Wp = Wh + (size_t)(ks * 64) * Dd + d;
            float acc[8];
#pragma unroll
            for (int i = 0; i < 8; i++) acc[i] = 0.0f;
#pragma unroll 4
            for (int kk = 0; kk < 64; kk++) {
                float w = Wp[(size_t)kk * Dd];
                float4 x0 = *(float4*)&xs[kk * 32 + bq * 8];
                float4 x1 = *(float4*)&xs[kk * 32 + bq * 8 + 4];
                acc[0] += w * x0.x; acc[1] += w * x0.y; acc[2] += w * x0.z; acc[3] += w * x0.w;
                acc[4] += w * x1.x; acc[5] += w * x1.y; acc[6] += w * x1.z; acc[7] += w * x1.w;
            }
#pragma unroll
            for (int i = 0; i < 8; i++)
                atomicAdd(&g_q[(bq * 8 + i) * Dd + d], acc[i]);
            __syncthreads();
        }
        gsync(nblk);

        // ---- scores: 1536 jobs (48 nt x 32 b), warp per n-row ----
        for (int job = bid; job < 1536; job += nblk) {
            int nt = job % 48, b = job / 48;
            float* qs = sh;
            float* vs = sh + 512;
            qs[tid] = g_q[b * Dd + tid];
            qs[tid + 256] = g_q[b * Dd + tid + 256];
            vs[tid] = vvec[tid];
            vs[tid + 256] = vvec[tid + 256];
            __syncthreads();
            int w = tid >> 5, lane = tid & 31;
            int n = nt * 8 + w;
            const float4* wv4 = (const float4*)(g_Wv + (size_t)(b * Nn + n) * Dd);
            const float4* q4 = (const float4*)qs;
            const float4* v4 = (const float4*)vs;
            float acc = 0.0f;
#pragma unroll
            for (int i = 0; i < 4; i++) {
                int id = i * 32 + lane;
                float4 a = wv4[id], q = q4[id], v = v4[id];
                acc += tanhf(a.x + q.x) * v.x;
                acc += tanhf(a.y + q.y) * v.y;
                acc += tanhf(a.z + q.z) * v.z;
                acc += tanhf(a.w + q.w) * v.w;
            }
#pragma unroll
            for (int off = 16; off > 0; off >>= 1)
                acc += __shfl_xor_sync(0xffffffffu, acc, off);
            if (lane == 0) g_sc[b * Nn + n] = acc;
            __syncthreads();
        }
        gsync(nblk);

        // ---- softmax + context + alpha: 128 jobs (4 strips x 32 b) ----
        for (int job = bid; job < 128; job += nblk) {
            int st = job & 3, b = job >> 2;
            float* al = sh;                            // [384]
            float* red = sh + 384;                     // [256]
            float m = -1e30f;
            for (int i = tid; i < Nn; i += 256) {
                float s = g_sc[b * Nn + i];
                al[i] = s;
                m = fmaxf(m, s);
            }
            red[tid] = m; __syncthreads();
            for (int o = 128; o > 0; o >>= 1) {
                if (tid < o) red[tid] = fmaxf(red[tid], red[tid + o]);
                __syncthreads();
            }
            m = red[0];
            __syncthreads();
            float sum = 0.0f;
            for (int i = tid; i < Nn; i += 256) {
                float e = expf(al[i] - m);
                al[i] = e;
                sum += e;
            }
            red[tid] = sum; __syncthreads();
            for (int o = 128; o > 0; o >>= 1) {
                if (tid < o) red[tid] += red[tid + o];
                __syncthreads();
            }
            float inv = 1.0f / red[0];
            __syncthreads();
            for (int i = tid; i < Nn; i += 256) al[i] *= inv;
            __syncthreads();

            if (st == 0) {
                float* ap = out_alpha + ((size_t)b * NSTEP + t) * Nn;
                for (int i = tid; i < Nn; i += 256) ap[i] = al[i];
            }
            // context partial: strip [st*96, st*96+96), 2 ways of 48 n each
            int c4 = tid & 127, way = tid >> 7;
            const float4* ep = (const float4*)enc + (size_t)b * Nn * 128 + c4;
            float4 acc = make_float4(0.f, 0.f, 0.f, 0.f);
            int n0 = st * 96 + way * 48;
#pragma unroll 4
            for (int n = n0; n < n0 + 48; n++) {
                float a = al[n];
                float4 ev = ep[(size_t)n * 128];
                acc.x += a * ev.x; acc.y += a * ev.y;
                acc.z += a * ev.z; acc.w += a * ev.w;
            }
            int c = c4 * 4;
            atomicAdd(&g_ctx[b * Cc + c + 0], acc.x);
            atomicAdd(&g_ctx[b * Cc + c + 1], acc.y);
            atomicAdd(&g_ctx[b * Cc + c + 2], acc.z);
            atomicAdd(&g_ctx[b * Cc + c + 3], acc.w);
            __syncthreads();
        }
        gsync(nblk);

        // ---- o_t partials + logits bias init: 139 jobs ----
        for (int job = bid; job < 139; job += nblk) {
            if (job >= 64) {
                int idx = (job - 64) * 256 + tid;      // < 32*600 = 19200
                if (idx < Bz * Vv) {
                    int b = idx / Vv, v = idx % Vv;
                    out_logits[((size_t)b * NSTEP + t) * Vv + v] = bout[v];
                }
            } else {
                float* xs = sh;                        // [128][32]
                int dt = job & 7, ks = job >> 3;
                for (int i = tid; i < 128 * 32; i += 256) {
                    int kk = i >> 5, b = i & 31;
                    int k = ks * 128 + kk;
                    xs[kk * 32 + b] = (k < 512) ? g_hx[b * Dd + k] : g_ctx[b * Cc + (k - 512)];
                }
                __syncthreads();
                int dl = tid & 63, bq = tid >> 6;
                int d = dt * 64 + dl;
                const float* Wp = Wc + (size_t)(ks * 128) * Dd + d;
                float acc[8];
#pragma unroll
                for (int i = 0; i < 8; i++) acc[i] = 0.0f;
#pragma unroll 4
                for (int kk = 0; kk < 128; kk++) {
                    float w = Wp[(size_t)kk * Dd];
                    float4 x0 = *(float4*)&xs[kk * 32 + bq * 8];
                    float4 x1 = *(float4*)&xs[kk * 32 + bq * 8 + 4];
                    acc[0] += w * x0.x; acc[1] += w * x0.y; acc[2] += w * x0.z; acc[3] += w * x0.w;
                    acc[4] += w * x1.x; acc[5] += w * x1.y; acc[6] += w * x1.z; acc[7] += w * x1.w;
                }
#pragma unroll
                for (int i = 0; i < 8; i++)
                    g_op[((size_t)ks * Bz + bq * 8 + i) * Dd + d] = acc[i];
            }
            __syncthreads();
        }
        gsync(nblk);

        // ---- logits = tanh(o_t) @ W_out (+ o_prev persist): 80 jobs ----
        for (int job = bid; job < 80; job += nblk) {
            float* os = sh;                            // [64][36] pitch 36
            int vt = job % 10, ds = job / 10;
            for (int i = tid; i < 64 * 32; i += 256) {
                int dl = i >> 5, b = i & 31;
                int d = ds * 64 + dl;
                float s = bc[d];
#pragma unroll
                for (int p = 0; p < 8; p++)
                    s += g_op[((size_t)p * Bz + b) * Dd + d];
                float o = tanhf(s);
                os[dl * 36 + b] = o;
                if (vt == 0) g_oprev[b * Dd + d] = o;
            }
            __syncthreads();
            int jj = tid & 63, bq = tid >> 6;
            int v = vt * 64 + jj;
            bool ok = (v < Vv);
            const float* Wp = Wout + (size_t)(ds * 64) * Vv + (ok ? v : 0);
            float acc[8];
#pragma unroll
            for (int i = 0; i < 8; i++) acc[i] = 0.0f;
#pragma unroll 4
            for (int kk = 0; kk < 64; kk++) {
                float w = Wp[(size_t)kk * Vv];
                float4 x0 = *(float4*)&os[kk * 36 + bq * 8];
                float4 x1 = *(float4*)&os[kk * 36 + bq * 8 + 4];
                acc[0] += w * x0.x; acc[1] += w * x0.y; acc[2] += w * x0.z; acc[3] += w * x0.w;
                acc[4] += w * x1.x; acc[5] += w * x1.y; acc[6] += w * x1.z; acc[7] += w * x1.w;
            }
            if (ok) {
#pragma unroll
                for (int i = 0; i < 8; i++) {
                    int b = bq * 8 + i;
                    atomicAdd(&out_logits[((size_t)b * NSTEP + t) * Vv + v], acc[i]);
                }
            }
            __syncthreads();
        }
        gsync(nblk);
    }
}

// ----------------------------- launch ---------------------------------------
extern "C" void kernel_launch(void* const* d_in, const int* in_sizes, int n_in,
                              void* d_out, int out_size) {
    const float* enc  = (const float*)d_in[0];
    const int*   tgt  = (const int*)d_in[1];         // int32 or int64, autodetected
    const float* emb  = (const float*)d_in[2];
    const float* Wih  = (const float*)d_in[3];
    const float* bih  = (const float*)d_in[4];
    const float* Whh  = (const float*)d_in[5];
    const float* bhh  = (const float*)d_in[6];
    const float* Wh   = (const float*)d_in[7];
    const float* Wvw  = (const float*)d_in[8];
    const float* vvec = (const float*)d_in[9];
    const float* Wc   = (const float*)d_in[10];
    const float* bc   = (const float*)d_in[11];
    const float* Wout = (const float*)d_in[12];
    const float* bout = (const float*)d_in[13];

    float* out_logits = (float*)d_out;                           // (32,191,600)
    float* out_alpha  = out_logits + (size_t)Bz * NSTEP * Vv;    // (32,191,384)

    int dev = 0;
    cudaGetDevice(&dev);
    int sms = 148;
    cudaDeviceGetAttribute(&sms, cudaDevAttrMultiProcessorCount, dev);
    int per = 0;
    cudaOccupancyMaxActiveBlocksPerMultiprocessor(&per, k_all, 256, 0);
    if (per < 1) per = 1;
    if (per > 4) per = 4;
    int nblk = sms * per;                            // exactly one resident wave

    k_all<<<nblk, 256>>>(enc, tgt, emb, Wih, bih, Whh, bhh, Wh, Wvw, vvec,
                         Wc, bc, Wout, bout, out_logits, out_alpha, nblk);
}

// round 12
// speedup vs baseline: 1.2111x; 1.2111x over previous
#include <cuda_runtime.h>
#include <cuda_bf16.h>

#define Bz 32
#define Nn 384          // H*W = 12*32
#define Cc 512
#define Dd 512
#define Ee 256
#define Vv 600
#define GJ 2048         // 4*D
#define NSTEP 191
#define EOS_TOK 130

// ----------------------------- scratch (device globals, no allocation) ------
__device__ float g_Wv[Bz * Nn * Dd];          // 24 MB   enc @ W_v, precomputed
__device__ float g_gp[8 * Bz * GJ];           // 2 MB    gates partials [ks][b][2048]
__device__ float g_op[8 * Bz * Dd];           // o_t partials [ks][b][d]
__device__ float g_hx[Bz * Dd];
__device__ float g_cx[Bz * Dd];
__device__ float g_oprev[Bz * Dd];
__device__ float g_q[Bz * Dd];
__device__ float g_ctx[Bz * Dd];
__device__ float g_sc[Bz * Nn];
__device__ int   g_tok[NSTEP * Bz];

// grid barrier state
__device__ unsigned g_count = 0;
__device__ volatile unsigned g_gen = 0;

// fast transcendentals (abs err ~1e-7, MUFU-light)
__device__ __forceinline__ float tanh_fast(float x) {
    float e = __expf(-2.0f * x);
    return __fdividef(2.0f, 1.0f + e) - 1.0f;
}
__device__ __forceinline__ float sig_fast(float x) {
    return __fdividef(1.0f, 1.0f + __expf(-x));
}

__device__ __forceinline__ void gsync(int nblk) {
    __syncthreads();
    if (threadIdx.x == 0) {
        __threadfence();
        unsigned gen = g_gen;
        unsigned t = atomicInc(&g_count, (unsigned)(nblk - 1)); // wraps at nblk-1
        if (t == (unsigned)(nblk - 1)) {
            __threadfence();
            g_gen = gen + 1;                 // release
        } else {
            while (g_gen == gen) { }         // spin (volatile load)
            __threadfence();                 // acquire
        }
    }
    __syncthreads();
}

// ============================ the whole decoder ==============================
__global__ void __launch_bounds__(256, 2) k_all(
    const float* __restrict__ enc, const int* __restrict__ tgt,
    const float* __restrict__ emb,
    const float* __restrict__ Wih, const float* __restrict__ bih,
    const float* __restrict__ Whh, const float* __restrict__ bhh,
    const float* __restrict__ Wh,  const float* __restrict__ Wvw,
    const float* __restrict__ vvec,
    const float* __restrict__ Wc,  const float* __restrict__ bc,
    const float* __restrict__ Wout,const float* __restrict__ bout,
    float* __restrict__ out_logits, float* __restrict__ out_alpha, int nblk)
{
    __shared__ float sh[6144];                       // 24 KB, reused per phase
    const int tid = threadIdx.x;
    const int bid = blockIdx.x;

    // -------------------- prologue: Wv GEMM + init + tokens -----------------
    for (int job = bid; job < 397; job += nblk) {
        if (job < 384) {
            int bm = job >> 2, bn = job & 3;
            int tm = tid / 16, tn = tid % 16;
            float acc[8][8];
#pragma unroll
            for (int i = 0; i < 8; i++)
#pragma unroll
                for (int j = 0; j < 8; j++) acc[i][j] = 0.0f;
            const float* Ag = enc + (size_t)(bm * 128) * 512;
            const float* Bg = Wvw + bn * 128;
            float* As = sh;            // [8][128]
            float* Bs = sh + 1024;     // [8][128]
            for (int k0 = 0; k0 < 512; k0 += 8) {
                {
                    int r = tid >> 1, s = tid & 1;
                    float4 a = *(const float4*)(Ag + (size_t)r * 512 + k0 + s * 4);
                    As[(s * 4 + 0) * 128 + r] = a.x; As[(s * 4 + 1) * 128 + r] = a.y;
                    As[(s * 4 + 2) * 128 + r] = a.z; As[(s * 4 + 3) * 128 + r] = a.w;
                }
                {
                    int kk = tid >> 5, c4 = tid & 31;
                    float4 bv = *(const float4*)(Bg + (size_t)(k0 + kk) * 512 + c4 * 4);
                    *(float4*)&Bs[kk * 128 + c4 * 4] = bv;
                }
                __syncthreads();
#pragma unroll
                for (int kk = 0; kk < 8; kk++) {
                    float a[8], b[8];
                    *(float4*)(a)     = *(float4*)&As[kk * 128 + tm * 8];
                    *(float4*)(a + 4) = *(float4*)&As[kk * 128 + tm * 8 + 4];
                    *(float4*)(b)     = *(float4*)&Bs[kk * 128 + tn * 8];
                    *(float4*)(b + 4) = *(float4*)&Bs[kk * 128 + tn * 8 + 4];
#pragma unroll
                    for (int i = 0; i < 8; i++)
#pragma unroll
                        for (int j = 0; j < 8; j++) acc[i][j] += a[i] * b[j];
                }
                __syncthreads();
            }
            float* Cg = g_Wv + (size_t)(bm * 128) * 512 + bn * 128;
#pragma unroll
            for (int i = 0; i < 8; i++) {
                int r = tm * 8 + i;
#pragma unroll
                for (int j = 0; j < 8; j += 4) {
                    float4 o = make_float4(acc[i][j], acc[i][j+1], acc[i][j+2], acc[i][j+3]);
                    *(float4*)(Cg + (size_t)r * 512 + tn * 8 + j) = o;
                }
            }
        } else if (job == 384) {
            // token precompute (int64/int32 autodetect: int64 high words are 0)
            if (tid == 0) {
                int nz = 0;
                for (int i = 1; i < 64; i += 2) nz |= tgt[i];
                ((int*)sh)[0] = (nz == 0) ? 1 : 0;
            }
            __syncthreads();
            int is64 = ((int*)sh)[0];
            if (tid < Bz) {
                int b = tid, fin = 0;
                g_tok[b] = 0;                         // sos
                for (int t = 0; t < NSTEP - 1; t++) {
                    int idx = b * 192 + t + 1;
                    int nt = is64 ? tgt[idx * 2] : tgt[idx];
                    fin |= (nt == EOS_TOK);
                    g_tok[(t + 1) * Bz + b] = fin ? 0 : nt;
                }
            }
        } else {
            int base = (job - 385) * 4096;            // 12 jobs x 4096 = 49152
            for (int i = tid; i < 4096; i += 256) {
                int idx = base + i;
                if (idx < 16384)        g_hx[idx] = 0.0f;
                else if (idx < 32768)   g_cx[idx - 16384] = 0.0f;
                else                    g_oprev[idx - 32768] = 0.0f;
            }
        }
        __syncthreads();
    }
    gsync(nblk);

    // ============================== step loop ===============================
    for (int t = 0; t < NSTEP; t++) {

        // ---- gates split-K GEMM: 256 jobs (32 jt x 8 ks), one round ----
        for (int job = bid; job < 256; job += nblk) {
            int jt = job & 31, ks = job >> 5;
            int kbase, klen;
            if (ks < 4) { kbase = ks * 192;            klen = 192; }
            else        { kbase = 768 + (ks - 4) * 128; klen = 128; }
            float* xs = sh;                            // [klen][32]
            for (int i = tid; i < klen * 32; i += 256) {
                int kk = i >> 5, b = i & 31;
                int k = kbase + kk;
                float xv;
                if (k < 256)      { int tok = g_tok[t * Bz + b]; xv = emb[tok * Ee + k]; }
                else if (k < 768) { xv = g_oprev[b * Dd + (k - 256)]; }
                else              { xv = g_hx[b * Dd + (k - 768)]; }
                xs[kk * 32 + b] = xv;
            }
            __syncthreads();
            int jj = tid & 63, bq = tid >> 6;
            int j = jt * 64 + jj;
            const float* Wp = (ks < 4) ? (Wih + (size_t)kbase * GJ + j)
                                       : (Whh + (size_t)(kbase - 768) * GJ + j);
            float acc[8];
#pragma unroll
            for (int i = 0; i < 8; i++) acc[i] = 0.0f;
#pragma unroll 16
            for (int kk = 0; kk < klen; kk++) {
                float w = Wp[(size_t)kk * GJ];
                float4 x0 = *(float4*)&xs[kk * 32 + bq * 8];
                float4 x1 = *(float4*)&xs[kk * 32 + bq * 8 + 4];
                acc[0] += w * x0.x; acc[1] += w * x0.y; acc[2] += w * x0.z; acc[3] += w * x0.w;
                acc[4] += w * x1.x; acc[5] += w * x1.y; acc[6] += w * x1.z; acc[7] += w * x1.w;
            }
#pragma unroll
            for (int i = 0; i < 8; i++)
                g_gp[((size_t)ks * Bz + bq * 8 + i) * GJ + j] = acc[i];
            __syncthreads();
        }
        gsync(nblk);

        // ---- LSTM elementwise (reduce 8 partials) + zero q/ctx ----
        for (int idx = bid * 256 + tid; idx < 16384; idx += nblk * 256) {
            int d = idx & 511;
            int b = idx >> 9;
            float gi = bih[d] + bhh[d];
            float gf = bih[d + 512] + bhh[d + 512];
            float gg = bih[d + 1024] + bhh[d + 1024];
            float go = bih[d + 1536] + bhh[d + 1536];
#pragma unroll
            for (int s = 0; s < 8; s++) {
                const float* gp = g_gp + ((size_t)s * Bz + b) * GJ;
                gi += gp[d];
                gf += gp[d + 512];
                gg += gp[d + 1024];
                go += gp[d + 1536];
            }
            float c = g_cx[idx];
            c = sig_fast(gf) * c + sig_fast(gi) * tanh_fast(gg);
            float h = sig_fast(go) * tanh_fast(c);
            g_cx[idx] = c;
            g_hx[idx] = h;
            g_q[idx] = 0.0f;
            g_ctx[idx] = 0.0f;
        }
        gsync(nblk);

        // ---- q = hx @ W_h: 64 jobs (8 dt x 8 ks), atomic accumulate ----
        for (int job = bid; job < 64; job += nblk) {
            int dt = job & 7, ks = job >> 3;
            float* xs = sh;                            // [64][32]
            for (int i = tid; i < 64 * 32; i += 256) {
                int kk = i >> 5, b = i & 31;
                xs[kk * 32 + b] = g_hx[b * Dd + ks * 64 + kk];
            }
            __syncthreads();
            int dl = tid & 63, bq = tid >> 6;
            int d = dt * 64 + dl;
            const float* Wp = Wh + (size_t)(ks * 64) * Dd + d;
            float acc[8];
#pragma unroll
            for (int i = 0; i < 8; i++) acc[i] = 0.0f;
#pragma unroll 16
            for (int kk = 0; kk < 64; kk++) {
                float w = Wp[(size_t)kk * Dd];
                float4 x0 = *(float4*)&xs[kk * 32 + bq * 8];
                float4 x1 = *(float4*)&xs[kk * 32 + bq * 8 + 4];
                acc[0] += w * x0.x; acc[1] += w * x0.y; acc[2] += w * x0.z; acc[3] += w * x0.w;
                acc[4] += w * x1.x; acc[5] += w * x1.y; acc[6] += w * x1.z; acc[7] += w * x1.w;
            }
#pragma unroll
            for (int i = 0; i < 8; i++)
                atomicAdd(&g_q[(bq * 8 + i) * Dd + d], acc[i]);
            __syncthreads();
        }
        gsync(nblk);

        // ---- scores: 768 jobs (24 nt x 32 b), warp handles 2 n-rows ----
        for (int job = bid; job < 768; job += nblk) {
            int nt = job % 24, b = job / 24;
            float* qs = sh;
            float* vs = sh + 512;
            qs[tid] = g_q[b * Dd + tid];
            qs[tid + 256] = g_q[b * Dd + tid + 256];
            vs[tid] = vvec[tid];
            vs[tid + 256] = vvec[tid + 256];
            __syncthreads();
            int w = tid >> 5, lane = tid & 31;
            int n0 = nt * 16 + w * 2;
            const float4* wv0 = (const float4*)(g_Wv + (size_t)(b * Nn + n0) * Dd);
            const float4* wv1 = (const float4*)(g_Wv + (size_t)(b * Nn + n0 + 1) * Dd);
            const float4* q4 = (const float4*)qs;
            const float4* v4 = (const float4*)vs;
            float acc0 = 0.0f, acc1 = 0.0f;
#pragma unroll
            for (int i = 0; i < 4; i++) {
                int id = i * 32 + lane;
                float4 a0 = wv0[id], a1 = wv1[id];
                float4 q = q4[id], v = v4[id];
                acc0 += tanh_fast(a0.x + q.x) * v.x;
                acc0 += tanh_fast(a0.y + q.y) * v.y;
                acc0 += tanh_fast(a0.z + q.z) * v.z;
                acc0 += tanh_fast(a0.w + q.w) * v.w;
                acc1 += tanh_fast(a1.x + q.x) * v.x;
                acc1 += tanh_fast(a1.y + q.y) * v.y;
                acc1 += tanh_fast(a1.z + q.z) * v.z;
                acc1 += tanh_fast(a1.w + q.w) * v.w;
            }
#pragma unroll
            for (int off = 16; off > 0; off >>= 1) {
                acc0 += __shfl_xor_sync(0xffffffffu, acc0, off);
                acc1 += __shfl_xor_sync(0xffffffffu, acc1, off);
            }
            if (lane == 0) {
                g_sc[b * Nn + n0] = acc0;
                g_sc[b * Nn + n0 + 1] = acc1;
            }
            __syncthreads();
        }
        gsync(nblk);

        // ---- softmax + context + alpha: 128 jobs (4 strips x 32 b) ----
        for (int job = bid; job < 128; job += nblk) {
            int st = job & 3, b = job >> 2;
            float* al = sh;                            // [384]
            float* red = sh + 384;                     // [256]
            float m = -1e30f;
            for (int i = tid; i < Nn; i += 256) {
                float s = g_sc[b * Nn + i];
                al[i] = s;
                m = fmaxf(m, s);
            }
            red[tid] = m; __syncthreads();
            for (int o = 128; o > 0; o >>= 1) {
                if (tid < o) red[tid] = fmaxf(red[tid], red[tid + o]);
                __syncthreads();
            }
            m = red[0];
            __syncthreads();
            float sum = 0.0f;
            for (int i = tid; i < Nn; i += 256) {
                float e = __expf(al[i] - m);
                al[i] = e;
                sum += e;
            }
            red[tid] = sum; __syncthreads();
            for (int o = 128; o > 0; o >>= 1) {
                if (tid < o) red[tid] += red[tid + o];
                __syncthreads();
            }
            float inv = __fdividef(1.0f, red[0]);
            __syncthreads();
            for (int i = tid; i < Nn; i += 256) al[i] *= inv;
            __syncthreads();

            if (st == 0) {
                float* ap = out_alpha + ((size_t)b * NSTEP + t) * Nn;
                for (int i = tid; i < Nn; i += 256) ap[i] = al[i];
            }
            // context partial: strip [st*96, st*96+96), 2 ways of 48 n each
            int c4 = tid & 127, way = tid >> 7;
            const float4* ep = (const float4*)enc + (size_t)b * Nn * 128 + c4;
            float4 acc = make_float4(0.f, 0.f, 0.f, 0.f);
            int n0 = st * 96 + way * 48;
#pragma unroll 8
            for (int n = n0; n < n0 + 48; n++) {
                float a = al[n];
                float4 ev = ep[(size_t)n * 128];
                acc.x += a * ev.x; acc.y += a * ev.y;
                acc.z += a * ev.z; acc.w += a * ev.w;
            }
            int c = c4 * 4;
            atomicAdd(&g_ctx[b * Cc + c + 0], acc.x);
            atomicAdd(&g_ctx[b * Cc + c + 1], acc.y);
            atomicAdd(&g_ctx[b * Cc + c + 2], acc.z);
            atomicAdd(&g_ctx[b * Cc + c + 3], acc.w);
            __syncthreads();
        }
        gsync(nblk);

        // ---- o_t partials + logits bias init: 139 jobs, one round ----
        for (int job = bid; job < 139; job += nblk) {
            if (job >= 64) {
                int idx = (job - 64) * 256 + tid;      // < 32*600 = 19200
                if (idx < Bz * Vv) {
                    int b = idx / Vv, v = idx % Vv;
                    out_logits[((size_t)b * NSTEP + t) * Vv + v] = bout[v];
                }
            } else {
                float* xs = sh;                        // [128][32]
                int dt = job & 7, ks = job >> 3;
                for (int i = tid; i < 128 * 32; i += 256) {
                    int kk = i >> 5, b = i & 31;
                    int k = ks * 128 + kk;
                    xs[kk * 32 + b] = (k < 512) ? g_hx[b * Dd + k] : g_ctx[b * Cc + (k - 512)];
                }
                __syncthreads();
                int dl = tid & 63, bq = tid >> 6;
                int d = dt * 64 + dl;
                const float* Wp = Wc + (size_t)(ks * 128) * Dd + d;
                float acc[8];
#pragma unroll
                for (int i = 0; i < 8; i++) acc[i] = 0.0f;
#pragma unroll 16
                for (int kk = 0; kk < 128; kk++) {
                    float w = Wp[(size_t)kk * Dd];
                    float4 x0 = *(float4*)&xs[kk * 32 + bq * 8];
                    float4 x1 = *(float4*)&xs[kk * 32 + bq * 8 + 4];
                    acc[0] += w * x0.x; acc[1] += w * x0.y; acc[2] += w * x0.z; acc[3] += w * x0.w;
                    acc[4] += w * x1.x; acc[5] += w * x1.y; acc[6] += w * x1.z; acc[7] += w * x1.w;
                }
#pragma unroll
                for (int i = 0; i < 8; i++)
                    g_op[((size_t)ks * Bz + bq * 8 + i) * Dd + d] = acc[i];
            }
            __syncthreads();
        }
        gsync(nblk);

        // ---- logits = tanh(o_t) @ W_out (+ o_prev persist): 80 jobs ----
        for (int job = bid; job < 80; job += nblk) {
            float* os = sh;                            // [64][36] pitch 36
            int vt = job % 10, ds = job / 10;
            for (int i = tid; i < 64 * 32; i += 256) {
                int dl = i >> 5, b = i & 31;
                int d = ds * 64 + dl;
                float s = bc[d];
#pragma unroll
                for (int p = 0; p < 8; p++)
                    s += g_op[((size_t)p * Bz + b) * Dd + d];
                float o = tanh_fast(s);
                os[dl * 36 + b] = o;
                if (vt == 0) g_oprev[b * Dd + d] = o;
            }
            __syncthreads();
            int jj = tid & 63, bq = tid >> 6;
            int v = vt * 64 + jj;
            bool ok = (v < Vv);
            const float* Wp = Wout + (size_t)(ds * 64) * Vv + (ok ? v : 0);
            float acc[8];
#pragma unroll
            for (int i = 0; i < 8; i++) acc[i] = 0.0f;
#pragma unroll 16
            for (int kk = 0; kk < 64; kk++) {
                float w = Wp[(size_t)kk * Vv];
                float4 x0 = *(float4*)&os[kk * 36 + bq * 8];
                float4 x1 = *(float4*)&os[kk * 36 + bq * 8 + 4];
                acc[0] += w * x0.x; acc[1] += w * x0.y; acc[2] += w * x0.z; acc[3] += w * x0.w;
                acc[4] += w * x1.x; acc[5] += w * x1.y; acc[6] += w * x1.z; acc[7] += w * x1.w;
            }
            if (ok) {
#pragma unroll
                for (int i = 0; i < 8; i++) {
                    int b = bq * 8 + i;
                    atomicAdd(&out_logits[((size_t)b * NSTEP + t) * Vv + v], acc[i]);
                }
            }
            __syncthreads();
        }
        gsync(nblk);
    }
}

// ----------------------------- launch ---------------------------------------
extern "C" void kernel_launch(void* const* d_in, const int* in_sizes, int n_in,
                              void* d_out, int out_size) {
    const float* enc  = (const float*)d_in[0];
    const int*   tgt  = (const int*)d_in[1];         // int32 or int64, autodetected
    const float* emb  = (const float*)d_in[2];
    const float* Wih  = (const float*)d_in[3];
    const float* bih  = (const float*)d_in[4];
    const float* Whh  = (const float*)d_in[5];
    const float* bhh  = (const float*)d_in[6];
    const float* Wh   = (const float*)d_in[7];
    const float* Wvw  = (const float*)d_in[8];
    const float* vvec = (const float*)d_in[9];
    const float* Wc   = (const float*)d_in[10];
    const float* bc   = (const float*)d_in[11];
    const float* Wout = (const float*)d_in[12];
    const float* bout = (const float*)d_in[13];

    float* out_logits = (float*)d_out;                           // (32,191,600)
    float* out_alpha  = out_logits + (size_t)Bz * NSTEP * Vv;    // (32,191,384)

    int dev = 0;
    cudaGetDevice(&dev);
    int sms = 148;
    cudaDeviceGetAttribute(&sms, cudaDevAttrMultiProcessorCount, dev);
    int per = 0;
    cudaOccupancyMaxActiveBlocksPerMultiprocessor(&per, k_all, 256, 0);
    if (per < 1) per = 1;
    if (per > 2) per = 2;
    int nblk = sms * per;                            // exactly one resident wave

    k_all<<<nblk, 256>>>(enc, tgt, emb, Wih, bih, Whh, bhh, Wh, Wvw, vvec,
                         Wc, bc, Wout, bout, out_logits, out_alpha, nblk);
}

// round 13
// speedup vs baseline: 1.5902x; 1.3130x over previous
#include <cuda_runtime.h>
#include <cuda_bf16.h>

#define Bz 32
#define Nn 384          // H*W = 12*32
#define Cc 512
#define Dd 512
#define Ee 256
#define Vv 600
#define GJ 2048         // 4*D
#define NSTEP 191
#define EOS_TOK 130

// ----------------------------- scratch (device globals, no allocation) ------
__device__ float g_Wv[Bz * Nn * Dd];          // 24 MB   enc @ W_v, precomputed
__device__ float g_gp[8 * Bz * GJ];           // gates partials [ks][b][2048]
__device__ float g_op[8 * Bz * Dd];           // o_t partials [ks][b][d]
__device__ float g_xT[1280 * Bz];             // transposed x: [emb|oprev|hx][b]
__device__ float g_cx[Bz * Dd];
__device__ float g_q[Bz * Dd];
__device__ float g_ctxT[Cc * Bz];             // transposed context [c][b]
__device__ float g_sc[Bz * Nn];
__device__ int   g_tok[NSTEP * Bz];

// grid barrier state
__device__ unsigned g_count = 0;
__device__ volatile unsigned g_gen = 0;

// fast transcendentals
__device__ __forceinline__ float tanh_mufu(float x) {      // 1 MUFU, abs err ~5e-4
    float y;
    asm("tanh.approx.f32 %0, %1;" : "=f"(y) : "f"(x));
    return y;
}
__device__ __forceinline__ float tanh_fast(float x) {      // 2 MUFU, err ~1e-7
    float e = __expf(-2.0f * x);
    return __fdividef(2.0f, 1.0f + e) - 1.0f;
}
__device__ __forceinline__ float sig_fast(float x) {
    return __fdividef(1.0f, 1.0f + __expf(-x));
}

__device__ __forceinline__ void gsync(int nblk) {
    __syncthreads();
    if (threadIdx.x == 0) {
        __threadfence();
        unsigned gen = g_gen;
        unsigned t = atomicInc(&g_count, (unsigned)(nblk - 1)); // wraps at nblk-1
        if (t == (unsigned)(nblk - 1)) {
            __threadfence();
            g_gen = gen + 1;                 // release
        } else {
            while (g_gen == gen) { }         // spin (volatile load)
            __threadfence();                 // acquire
        }
    }
    __syncthreads();
}

// ============================ the whole decoder ==============================
__global__ void __launch_bounds__(256, 2) k_all(
    const float* __restrict__ enc, const int* __restrict__ tgt,
    const float* __restrict__ emb,
    const float* __restrict__ Wih, const float* __restrict__ bih,
    const float* __restrict__ Whh, const float* __restrict__ bhh,
    const float* __restrict__ Wh,  const float* __restrict__ Wvw,
    const float* __restrict__ vvec,
    const float* __restrict__ Wc,  const float* __restrict__ bc,
    const float* __restrict__ Wout,const float* __restrict__ bout,
    float* __restrict__ out_logits, float* __restrict__ out_alpha, int nblk)
{
    __shared__ float sh[6144];                       // 24 KB, reused per phase
    const int tid = threadIdx.x;
    const int bid = blockIdx.x;

    // -------------------- prologue: Wv GEMM + init + tokens -----------------
    // jobs: [0,384) Wv tiles; 384 tokens; [385,399) zero xT (40960) + cx (16384)
    for (int job = bid; job < 399; job += nblk) {
        if (job < 384) {
            int bm = job >> 2, bn = job & 3;
            int tm = tid / 16, tn = tid % 16;
            float acc[8][8];
#pragma unroll
            for (int i = 0; i < 8; i++)
#pragma unroll
                for (int j = 0; j < 8; j++) acc[i][j] = 0.0f;
            const float* Ag = enc + (size_t)(bm * 128) * 512;
            const float* Bg = Wvw + bn * 128;
            float* As = sh;            // [8][128]
            float* Bs = sh + 1024;     // [8][128]
            for (int k0 = 0; k0 < 512; k0 += 8) {
                {
                    int r = tid >> 1, s = tid & 1;
                    float4 a = *(const float4*)(Ag + (size_t)r * 512 + k0 + s * 4);
                    As[(s * 4 + 0) * 128 + r] = a.x; As[(s * 4 + 1) * 128 + r] = a.y;
                    As[(s * 4 + 2) * 128 + r] = a.z; As[(s * 4 + 3) * 128 + r] = a.w;
                }
                {
                    int kk = tid >> 5, c4 = tid & 31;
                    float4 bv = *(const float4*)(Bg + (size_t)(k0 + kk) * 512 + c4 * 4);
                    *(float4*)&Bs[kk * 128 + c4 * 4] = bv;
                }
                __syncthreads();
#pragma unroll
                for (int kk = 0; kk < 8; kk++) {
                    float a[8], b[8];
                    *(float4*)(a)     = *(float4*)&As[kk * 128 + tm * 8];
                    *(float4*)(a + 4) = *(float4*)&As[kk * 128 + tm * 8 + 4];
                    *(float4*)(b)     = *(float4*)&Bs[kk * 128 + tn * 8];
                    *(float4*)(b + 4) = *(float4*)&Bs[kk * 128 + tn * 8 + 4];
#pragma unroll
                    for (int i = 0; i < 8; i++)
#pragma unroll
                        for (int j = 0; j < 8; j++) acc[i][j] += a[i] * b[j];
                }
                __syncthreads();
            }
            float* Cg = g_Wv + (size_t)(bm * 128) * 512 + bn * 128;
#pragma unroll
            for (int i = 0; i < 8; i++) {
                int r = tm * 8 + i;
#pragma unroll
                for (int j = 0; j < 8; j += 4) {
                    float4 o = make_float4(acc[i][j], acc[i][j+1], acc[i][j+2], acc[i][j+3]);
                    *(float4*)(Cg + (size_t)r * 512 + tn * 8 + j) = o;
                }
            }
        } else if (job == 384) {
            // token precompute (int64/int32 autodetect: int64 high words are 0)
            if (tid == 0) {
                int nz = 0;
                for (int i = 1; i < 64; i += 2) nz |= tgt[i];
                ((int*)sh)[0] = (nz == 0) ? 1 : 0;
            }
            __syncthreads();
            int is64 = ((int*)sh)[0];
            if (tid < Bz) {
                int b = tid, fin = 0;
                g_tok[b] = 0;                         // sos
                for (int t = 0; t < NSTEP - 1; t++) {
                    int idx = b * 192 + t + 1;
                    int nt = is64 ? tgt[idx * 2] : tgt[idx];
                    fin |= (nt == EOS_TOK);
                    g_tok[(t + 1) * Bz + b] = fin ? 0 : nt;
                }
            }
        } else {
            int base = (job - 385) * 4096;            // 14 jobs x 4096 = 57344
            for (int i = tid; i < 4096; i += 256) {
                int idx = base + i;
                if (idx < 40960)        g_xT[idx] = 0.0f;      // emb(tok=0)=0, oprev=0, hx=0
                else if (idx < 57344)   g_cx[idx - 40960] = 0.0f;
            }
        }
        __syncthreads();
    }
    gsync(nblk);

    // ============================== step loop ===============================
    for (int t = 0; t < NSTEP; t++) {

        // ---- gates split-K GEMM: 256 jobs (32 jt x 8 ks) ----
        for (int job = bid; job < 256; job += nblk) {
            int jt = job & 31, ks = job >> 5;
            int kbase, klen;
            if (ks < 4) { kbase = ks * 192;             klen = 192; }
            else        { kbase = 768 + (ks - 4) * 128; klen = 128; }
            float* xs = sh;                            // [klen][32]
            // coalesced fill from g_xT (float4 both sides, conflict-free)
            for (int i4 = tid; i4 < klen * 8; i4 += 256) {
                int kk = i4 >> 3, b4 = i4 & 7;
                float4 v = ((const float4*)(g_xT + (size_t)(kbase + kk) * 32))[b4];
                ((float4*)(xs + kk * 32))[b4] = v;
            }
            __syncthreads();
            int jj = tid & 63, bq = tid >> 6;
            int j = jt * 64 + jj;
            const float* Wp = (ks < 4) ? (Wih + (size_t)kbase * GJ + j)
                                       : (Whh + (size_t)(kbase - 768) * GJ + j);
            float acc[8];
#pragma unroll
            for (int i = 0; i < 8; i++) acc[i] = 0.0f;
#pragma unroll 16
            for (int kk = 0; kk < klen; kk++) {
                float w = Wp[(size_t)kk * GJ];
                float4 x0 = *(float4*)&xs[kk * 32 + bq * 8];
                float4 x1 = *(float4*)&xs[kk * 32 + bq * 8 + 4];
                acc[0] += w * x0.x; acc[1] += w * x0.y; acc[2] += w * x0.z; acc[3] += w * x0.w;
                acc[4] += w * x1.x; acc[5] += w * x1.y; acc[6] += w * x1.z; acc[7] += w * x1.w;
            }
#pragma unroll
            for (int i = 0; i < 8; i++)
                g_gp[((size_t)ks * Bz + bq * 8 + i) * GJ + j] = acc[i];
            __syncthreads();
        }
        gsync(nblk);

        // ---- LSTM elementwise (reduce 8 partials) + zero q/ctxT, write hxT ----
        for (int idx = bid * 256 + tid; idx < 16384; idx += nblk * 256) {
            int d = idx & 511;
            int b = idx >> 9;
            float gi = bih[d] + bhh[d];
            float gf = bih[d + 512] + bhh[d + 512];
            float gg = bih[d + 1024] + bhh[d + 1024];
            float go = bih[d + 1536] + bhh[d + 1536];
#pragma unroll
            for (int s = 0; s < 8; s++) {
                const float* gp = g_gp + ((size_t)s * Bz + b) * GJ;
                gi += gp[d];
                gf += gp[d + 512];
                gg += gp[d + 1024];
                go += gp[d + 1536];
            }
            float c = g_cx[idx];
            c = sig_fast(gf) * c + sig_fast(gi) * tanh_fast(gg);
            float h = sig_fast(go) * tanh_fast(c);
            g_cx[idx] = c;
            g_xT[(768 + d) * 32 + b] = h;            // transposed hx
            g_q[idx] = 0.0f;
            g_ctxT[idx] = 0.0f;
        }
        gsync(nblk);

        // ---- q = hx @ W_h: 128 jobs (8 dt x 16 ks of K=32), atomic accum ----
        for (int job = bid; job < 128; job += nblk) {
            int dt = job & 7, ks = job >> 3;
            float* xs = sh;                            // [32][32]
            for (int i4 = tid; i4 < 256; i4 += 256) {
                int kk = i4 >> 3, b4 = i4 & 7;
                float4 v = ((const float4*)(g_xT + (size_t)(768 + ks * 32 + kk) * 32))[b4];
                ((float4*)(xs + kk * 32))[b4] = v;
            }
            __syncthreads();
            int dl = tid & 63, bq = tid >> 6;
            int d = dt * 64 + dl;
            const float* Wp = Wh + (size_t)(ks * 32) * Dd + d;
            float acc[8];
#pragma unroll
            for (int i = 0; i < 8; i++) acc[i] = 0.0f;
#pragma unroll 16
            for (int kk = 0; kk < 32; kk++) {
                float w = Wp[(size_t)kk * Dd];
                float4 x0 = *(float4*)&xs[kk * 32 + bq * 8];
                float4 x1 = *(float4*)&xs[kk * 32 + bq * 8 + 4];
                acc[0] += w * x0.x; acc[1] += w * x0.y; acc[2] += w * x0.z; acc[3] += w * x0.w;
                acc[4] += w * x1.x; acc[5] += w * x1.y; acc[6] += w * x1.z; acc[7] += w * x1.w;
            }
#pragma unroll
            for (int i = 0; i < 8; i++)
                atomicAdd(&g_q[(bq * 8 + i) * Dd + d], acc[i]);
            __syncthreads();
        }
        gsync(nblk);

        // ---- scores: 608 jobs (19 tiles x 32 b) = exactly 2 rounds ----
        for (int job = bid; job < 608; job += nblk) {
            int nt = job % 19, b = job / 19;
            float* qs = sh;
            float* vs = sh + 512;
            qs[tid] = g_q[b * Dd + tid];
            qs[tid + 256] = g_q[b * Dd + tid + 256];
            vs[tid] = vvec[tid];
            vs[tid + 256] = vvec[tid + 256];
            __syncthreads();
            int w = tid >> 5, lane = tid & 31;
            int n0 = nt * 20;
            int cnt = (nt == 18) ? 24 : 20;
            const float4* q4 = (const float4*)qs;
            const float4* v4 = (const float4*)vs;
            for (int r = w; r < cnt; r += 8) {
                int n = n0 + r;
                const float4* wv = (const float4*)(g_Wv + (size_t)(b * Nn + n) * Dd);
                float acc = 0.0f;
#pragma unroll
                for (int i = 0; i < 4; i++) {
                    int id = i * 32 + lane;
                    float4 a = wv[id], q = q4[id], v = v4[id];
                    acc += tanh_mufu(a.x + q.x) * v.x;
                    acc += tanh_mufu(a.y + q.y) * v.y;
                    acc += tanh_mufu(a.z + q.z) * v.z;
                    acc += tanh_mufu(a.w + q.w) * v.w;
                }
#pragma unroll
                for (int off = 16; off > 0; off >>= 1)
                    acc += __shfl_xor_sync(0xffffffffu, acc, off);
                if (lane == 0) g_sc[b * Nn + n] = acc;
            }
            __syncthreads();
        }
        gsync(nblk);

        // ---- softmax + context + alpha: 256 jobs (8 strips x 32 b) ----
        for (int job = bid; job < 256; job += nblk) {
            int st = job & 7, b = job >> 3;
            float* al = sh;                            // [384]
            float* red = sh + 384;                     // [256]
            float m = -1e30f;
            for (int i = tid; i < Nn; i += 256) {
                float s = g_sc[b * Nn + i];
                al[i] = s;
                m = fmaxf(m, s);
            }
            red[tid] = m; __syncthreads();
            for (int o = 128; o > 0; o >>= 1) {
                if (tid < o) red[tid] = fmaxf(red[tid], red[tid + o]);
                __syncthreads();
            }
            m = red[0];
            __syncthreads();
            float sum = 0.0f;
            for (int i = tid; i < Nn; i += 256) {
                float e = __expf(al[i] - m);
                al[i] = e;
                sum += e;
            }
            red[tid] = sum; __syncthreads();
            for (int o = 128; o > 0; o >>= 1) {
                if (tid < o) red[tid] += red[tid + o];
                __syncthreads();
            }
            float inv = __fdividef(1.0f, red[0]);
            __syncthreads();
            for (int i = tid; i < Nn; i += 256) al[i] *= inv;
            __syncthreads();

            if (st == 0) {
                float* ap = out_alpha + ((size_t)b * NSTEP + t) * Nn;
                for (int i = tid; i < Nn; i += 256) ap[i] = al[i];
            }
            // context partial: strip of 48 n, 2 ways of 24 n
            int c4 = tid & 127, way = tid >> 7;
            const float4* ep = (const float4*)enc + (size_t)b * Nn * 128 + c4;
            float4 acc = make_float4(0.f, 0.f, 0.f, 0.f);
            int n0 = st * 48 + way * 24;
#pragma unroll 8
            for (int n = n0; n < n0 + 24; n++) {
                float a = al[n];
                float4 ev = ep[(size_t)n * 128];
                acc.x += a * ev.x; acc.y += a * ev.y;
                acc.z += a * ev.z; acc.w += a * ev.w;
            }
            int c = c4 * 4;
            atomicAdd(&g_ctxT[(c + 0) * 32 + b], acc.x);
            atomicAdd(&g_ctxT[(c + 1) * 32 + b], acc.y);
            atomicAdd(&g_ctxT[(c + 2) * 32 + b], acc.z);
            atomicAdd(&g_ctxT[(c + 3) * 32 + b], acc.w);
            __syncthreads();
        }
        gsync(nblk);

        // ---- o_t partials + logits bias init: 203 jobs ----
        for (int job = bid; job < 203; job += nblk) {
            if (job >= 128) {
                int idx = (job - 128) * 256 + tid;     // < 32*600 = 19200
                if (idx < Bz * Vv) {
                    int b = idx / Vv, v = idx % Vv;
                    out_logits[((size_t)b * NSTEP + t) * Vv + v] = bout[v];
                }
            } else {
                // (dt 0..7, ks 0..7, bh 0..1): 16 b per job, K=128
                float* xs = sh;                        // [128][16]
                int dt = job & 7, ks = (job >> 3) & 7, bh = job >> 6;
                for (int i4 = tid; i4 < 512; i4 += 256) {
                    int kk = i4 >> 2, b4 = i4 & 3;
                    int k = ks * 128 + kk;
                    const float* src = (k < 512) ? (g_xT + (size_t)(768 + k) * 32)
                                                 : (g_ctxT + (size_t)(k - 512) * 32);
                    float4 v = ((const float4*)(src + bh * 16))[b4];
                    ((float4*)(xs + kk * 16))[b4] = v;
                }
                __syncthreads();
                int dl = tid & 63, bq = tid >> 6;      // bq 0..3, 4 b each
                int d = dt * 64 + dl;
                const float* Wp = Wc + (size_t)(ks * 128) * Dd + d;
                float acc[4];
#pragma unroll
                for (int i = 0; i < 4; i++) acc[i] = 0.0f;
#pragma unroll 16
                for (int kk = 0; kk < 128; kk++) {
                    float w = Wp[(size_t)kk * Dd];
                    float4 x0 = *(float4*)&xs[kk * 16 + bq * 4];
                    acc[0] += w * x0.x; acc[1] += w * x0.y;
                    acc[2] += w * x0.z; acc[3] += w * x0.w;
                }
#pragma unroll
                for (int i = 0; i < 4; i++)
                    g_op[((size_t)ks * Bz + bh * 16 + bq * 4 + i) * Dd + d] = acc[i];
            }
            __syncthreads();
        }
        gsync(nblk);

        // ---- logits + o_prevT persist + embT(t+1) prefetch: 168 jobs ----
        for (int job = bid; job < 168; job += nblk) {
            if (job >= 160) {
                // prefetch transposed embeddings for step t+1
                if (t + 1 < NSTEP) {
                    int j8 = job - 160;                // 8 jobs x 32 k-rows
                    for (int i = tid; i < 1024; i += 256) {
                        int k = j8 * 32 + (i >> 5), b = i & 31;
                        int tok = g_tok[(t + 1) * Bz + b];
                        g_xT[k * 32 + b] = emb[tok * Ee + k];
                    }
                }
            } else {
                // (vt 0..9, ds 0..7, bh 0..1): 16 b, K=64
                float* os = sh;                        // [64][pitch 20]
                int vt = job % 10, ds = (job / 10) & 7, bh = job / 80;
                for (int i = tid; i < 1024; i += 256) {
                    int b = i >> 6, dl = i & 63;       // b 0..15 local
                    int gb = bh * 16 + b;
                    int d = ds * 64 + dl;
                    float s = bc[d];
#pragma unroll
                    for (int p = 0; p < 8; p++)
                        s += g_op[((size_t)p * Bz + gb) * Dd + d];
                    float o = tanh_fast(s);
                    os[dl * 20 + b] = o;
                    if (vt == 0) g_xT[(256 + d) * 32 + gb] = o;   // o_prevT
                }
                __syncthreads();
                int jj = tid & 63, bq = tid >> 6;      // 4 bq x 4 b
                int v = vt * 64 + jj;
                bool ok = (v < Vv);
                const float* Wp = Wout + (size_t)(ds * 64) * Vv + (ok ? v : 0);
                float acc[4];
#pragma unroll
                for (int i = 0; i < 4; i++) acc[i] = 0.0f;
#pragma unroll 16
                for (int kk = 0; kk < 64; kk++) {
                    float w = Wp[(size_t)kk * Vv];
                    float4 x0 = *(float4*)&os[kk * 20 + bq * 4];
                    acc[0] += w * x0.x; acc[1] += w * x0.y;
                    acc[2] += w * x0.z; acc[3] += w * x0.w;
                }
                if (ok) {
#pragma unroll
                    for (int i = 0; i < 4; i++) {
                        int b = bh * 16 + bq * 4 + i;
                        atomicAdd(&out_logits[((size_t)b * NSTEP + t) * Vv + v], acc[i]);
                    }
                }
            }
            __syncthreads();
        }
        gsync(nblk);
    }
}

// ----------------------------- launch ---------------------------------------
extern "C" void kernel_launch(void* const* d_in, const int* in_sizes, int n_in,
                              void* d_out, int out_size) {
    const float* enc  = (const float*)d_in[0];
    const int*   tgt  = (const int*)d_in[1];         // int32 or int64, autodetected
    const float* emb  = (const float*)d_in[2];
    const float* Wih  = (const float*)d_in[3];
    const float* bih  = (const float*)d_in[4];
    const float* Whh  = (const float*)d_in[5];
    const float* bhh  = (const float*)d_in[6];
    const float* Wh   = (const float*)d_in[7];
    const float* Wvw  = (const float*)d_in[8];
    const float* vvec = (const float*)d_in[9];
    const float* Wc   = (const float*)d_in[10];
    const float* bc   = (const float*)d_in[11];
    const float* Wout = (const float*)d_in[12];
    const float* bout = (const float*)d_in[13];

    float* out_logits = (float*)d_out;                           // (32,191,600)
    float* out_alpha  = out_logits + (size_t)Bz * NSTEP * Vv;    // (32,191,384)

    int dev = 0;
    cudaGetDevice(&dev);
    int sms = 148;
    cudaDeviceGetAttribute(&sms, cudaDevAttrMultiProcessorCount, dev);
    int per = 0;
    cudaOccupancyMaxActiveBlocksPerMultiprocessor(&per, k_all, 256, 0);
    if (per < 1) per = 1;
    if (per > 2) per = 2;
    int nblk = sms * per;                            // one resident wave

    k_all<<<nblk, 256>>>(enc, tgt, emb, Wih, bih, Whh, bhh, Wh, Wvw, vvec,
                         Wc, bc, Wout, bout, out_logits, out_alpha, nblk);
}